// round 6
// baseline (speedup 1.0000x reference)
#include <cuda_runtime.h>

// Problem constants
#define CELLS 64              // B*S = 8*8
#define HW 262144             // 512*512
#define HW4 65536             // HW / 4 (float4 count per cell)
#define CHUNKS 32             // blocks per cell
#define THREADS 256
#define F4_PER_THREAD 8       // 32*256*8 = 65536 = HW4

// Per-(cell,chunk) partials: 6 sums each. Every slot is written by exactly one
// block on every run (plain stores, no atomics) -> no zero-init launch needed,
// fully deterministic across graph replays.
__device__ float g_part[CELLS][CHUNKS][6];

__global__ void __launch_bounds__(THREADS) reduce_kernel(
    const float4* __restrict__ probs,     // seg_probs
    const float4* __restrict__ targs,     // seg_targets (0/1)
    const float4* __restrict__ attn)      // attention_maps
{
    const int cell  = blockIdx.y;
    const int chunk = blockIdx.x;
    long base = (long)cell * HW4 + (long)chunk * (THREADS * F4_PER_THREAD) + threadIdx.x;

    float s_bce = 0.f, s_foc = 0.f, s_ptv = 0.f, s_p = 0.f, s_t = 0.f, s_att = 0.f;

#pragma unroll
    for (int it = 0; it < F4_PER_THREAD; it++) {
        long idx = base + (long)it * THREADS;
        float4 p = probs[idx];
        float4 t = targs[idx];
        float4 a = attn[idx];

        const float* pv = &p.x;
        const float* tv = &t.x;
        const float* av = &a.x;
#pragma unroll
        for (int k = 0; k < 4; k++) {
            float pk = pv[k], tk = tv[k], ak = av[k];
            // t in {0,1}:  pt_val = t ? p : (1-p) = 1 - p - t + 2pt = exp(-bce)
            float ptval = fmaf(2.f * pk, tk, 1.f - pk - tk);
            float l = __logf(ptval);            // bce = -l
            s_bce -= l;
            float om = 1.f - ptval;
            s_foc -= om * om * l;               // (1-pt)^2 * bce (alpha folded later)
            s_ptv = fmaf(pk, tk, s_ptv);
            s_p  += pk;
            s_t  += tk;
            // attention BCE with target==t: -log(t ? a : 1-a)
            float aval = fmaf(2.f * ak, tk, 1.f - ak - tk);
            s_att -= __logf(aval);
        }
    }

    // warp reduce the 6 sums
    float s[6] = {s_bce, s_foc, s_ptv, s_p, s_t, s_att};
#pragma unroll
    for (int j = 0; j < 6; j++) {
#pragma unroll
        for (int off = 16; off > 0; off >>= 1)
            s[j] += __shfl_xor_sync(0xffffffffu, s[j], off);
    }

    __shared__ float sh[THREADS / 32][6];
    int warp = threadIdx.x >> 5, lane = threadIdx.x & 31;
    if (lane == 0) {
#pragma unroll
        for (int j = 0; j < 6; j++) sh[warp][j] = s[j];
    }
    __syncthreads();
    if (threadIdx.x < 6) {
        float v = 0.f;
#pragma unroll
        for (int w = 0; w < THREADS / 32; w++) v += sh[w][threadIdx.x];
        g_part[cell][chunk][threadIdx.x] = v;   // unique slot, plain store
    }
}

__global__ void __launch_bounds__(THREADS) final_kernel(
    const float* __restrict__ presence_probs,
    const int*   __restrict__ presence_targets,
    float*       __restrict__ out)
{
    __shared__ float sh_cs[CELLS][6];    // per-cell component sums
    __shared__ float sh_terms[CELLS][7]; // per-cell loss terms

    // Phase 1: reduce CHUNKS partials per (cell, component). 384 jobs, 256 thr.
    for (int job = threadIdx.x; job < CELLS * 6; job += THREADS) {
        int c = job / 6, comp = job % 6;
        float v = 0.f;
#pragma unroll
        for (int ch = 0; ch < CHUNKS; ch++) v += g_part[c][ch][comp];
        sh_cs[c][comp] = v;
    }
    __syncthreads();

    // Phase 2: per-cell loss terms.
    if (threadIdx.x < CELLS) {
        int c = threadIdx.x;
        const float inv_hw = 1.0f / (float)HW;
        float sb  = sh_cs[c][0];
        float sf  = sh_cs[c][1];
        float spt = sh_cs[c][2];
        float sp  = sh_cs[c][3];
        float st  = sh_cs[c][4];
        float sa  = sh_cs[c][5];

        float pres = (float)presence_targets[c];
        float pp   = presence_probs[c];

        float bce_mean   = sb * inv_hw;
        float focal_mean = 0.25f * sf * inv_hw;   // FOCAL_ALPHA
        float dice       = 1.f - (2.f * spt + 1e-6f) / (sp + st + 1e-6f);
        float att_mean   = sa * inv_hw;

        // absence BCE (pp in (1e-4, 1-1e-4): reference clamps inert)
        float absence = -(pres * logf(pp) + (1.f - pres) * logf(1.f - pp));

        bool wrong = ((pres == 0.f) && (pp > 0.5f)) || ((pres == 1.f) && (pp < 0.5f));
        float d = pp - 0.5f;
        float conf = wrong ? d * d : 0.f;

        sh_terms[c][0] = pres;
        sh_terms[c][1] = bce_mean   * pres;
        sh_terms[c][2] = dice       * pres;
        sh_terms[c][3] = focal_mean * pres;
        sh_terms[c][4] = absence;
        sh_terms[c][5] = att_mean   * pres;
        sh_terms[c][6] = conf;
    }
    __syncthreads();

    // Phase 3: combine into the scalar.
    if (threadIdx.x == 0) {
        float cnt = 0.f, Sseg = 0.f, Sdice = 0.f, Sfoc = 0.f,
              Sabs = 0.f, Satt = 0.f, Sconf = 0.f;
        for (int i = 0; i < CELLS; i++) {
            cnt   += sh_terms[i][0];
            Sseg  += sh_terms[i][1];
            Sdice += sh_terms[i][2];
            Sfoc  += sh_terms[i][3];
            Sabs  += sh_terms[i][4];
            Satt  += sh_terms[i][5];
            Sconf += sh_terms[i][6];
        }
        float safe = fmaxf(cnt, 1.f);
        float seg_loss   = (cnt > 0.f) ? Sseg  / safe : 0.f;
        float dice_loss  = (cnt > 0.f) ? Sdice / safe : 0.f;
        float focal_loss = (cnt > 0.f) ? Sfoc  / safe : 0.f;
        float n_cells = (float)CELLS;

        out[0] = 1.0f * seg_loss
               + 1.0f * dice_loss
               + 0.5f * focal_loss
               + 1.0f * (Sabs / n_cells)
               + 0.5f * (Satt / n_cells)
               + 0.1f * (Sconf / n_cells);
    }
}

extern "C" void kernel_launch(void* const* d_in, const int* in_sizes, int n_in,
                              void* d_out, int out_size)
{
    // metadata order: seg_logits, seg_probs, seg_targets, presence_probs,
    //                 attention_maps, presence_targets
    // seg_logits (d_in[0]) is redundant: probs = sigmoid(logits) is given and
    // targets are exactly {0,1}, so bce = -log(t ? p : 1-p).
    const float4* probs = (const float4*)d_in[1];
    const float4* targs = (const float4*)d_in[2];
    const float*  pp    = (const float*)d_in[3];
    const float4* attn  = (const float4*)d_in[4];
    const int*    pt    = (const int*)d_in[5];
    float* out = (float*)d_out;

    dim3 grid(CHUNKS, CELLS);
    reduce_kernel<<<grid, THREADS>>>(probs, targs, attn);
    final_kernel<<<1, THREADS>>>(pp, pt, out);
}

// round 7
// speedup vs baseline: 1.0983x; 1.0983x over previous
#include <cuda_runtime.h>

// Problem constants
#define CELLS 64              // B*S = 8*8
#define HW 262144             // 512*512
#define HW4 65536             // HW / 4 (float4 count per cell)
#define CHUNKS 32             // blocks per cell
#define THREADS 256
#define F4_PER_THREAD 8       // 32*256*8 = 65536 = HW4

// Per-cell accumulators (tiny: 1.5 KB). Zero at module load; each replay:
// reduce_kernel atomically accumulates, final_kernel reads then resets to
// zero for the next replay. Deterministic under stream ordering.
__device__ float g_acc[CELLS][6];

__global__ void __launch_bounds__(THREADS) reduce_kernel(
    const float4* __restrict__ probs,     // seg_probs
    const float4* __restrict__ targs,     // seg_targets (0/1)
    const float4* __restrict__ attn)      // attention_maps
{
    const int cell  = blockIdx.y;
    const int chunk = blockIdx.x;
    long base = (long)cell * HW4 + (long)chunk * (THREADS * F4_PER_THREAD) + threadIdx.x;

    float s_bce = 0.f, s_foc = 0.f, s_ptv = 0.f, s_p = 0.f, s_t = 0.f, s_att = 0.f;

#pragma unroll
    for (int it = 0; it < F4_PER_THREAD; it++) {
        long idx = base + (long)it * THREADS;
        float4 p = probs[idx];
        float4 t = targs[idx];
        float4 a = attn[idx];

        const float* pv = &p.x;
        const float* tv = &t.x;
        const float* av = &a.x;
#pragma unroll
        for (int k = 0; k < 4; k++) {
            float pk = pv[k], tk = tv[k], ak = av[k];
            // t in {0,1}:  pt_val = t ? p : (1-p) = 1 - p - t + 2pt = exp(-bce)
            float ptval = fmaf(2.f * pk, tk, 1.f - pk - tk);
            float l = __logf(ptval);            // bce = -l
            s_bce -= l;
            float om = 1.f - ptval;
            s_foc -= om * om * l;               // (1-pt)^2 * bce (alpha folded later)
            s_ptv = fmaf(pk, tk, s_ptv);
            s_p  += pk;
            s_t  += tk;
            // attention BCE with target==t: -log(t ? a : 1-a)
            float aval = fmaf(2.f * ak, tk, 1.f - ak - tk);
            s_att -= __logf(aval);
        }
    }

    // warp reduce the 6 sums
    float s[6] = {s_bce, s_foc, s_ptv, s_p, s_t, s_att};
#pragma unroll
    for (int j = 0; j < 6; j++) {
#pragma unroll
        for (int off = 16; off > 0; off >>= 1)
            s[j] += __shfl_xor_sync(0xffffffffu, s[j], off);
    }

    __shared__ float sh[THREADS / 32][6];
    int warp = threadIdx.x >> 5, lane = threadIdx.x & 31;
    if (lane == 0) {
#pragma unroll
        for (int j = 0; j < 6; j++) sh[warp][j] = s[j];
    }
    __syncthreads();
    if (threadIdx.x < 6) {
        float v = 0.f;
#pragma unroll
        for (int w = 0; w < THREADS / 32; w++) v += sh[w][threadIdx.x];
        atomicAdd(&g_acc[cell][threadIdx.x], v);
    }
}

__global__ void __launch_bounds__(384) final_kernel(
    const float* __restrict__ presence_probs,
    const int*   __restrict__ presence_targets,
    float*       __restrict__ out)
{
    __shared__ float sh_cs[CELLS][6];    // per-cell component sums
    __shared__ float sh_terms[CELLS][7]; // per-cell loss terms

    // Phase 1: read accumulators (384 floats), then reset for next replay.
    if (threadIdx.x < CELLS * 6) {
        int c = threadIdx.x / 6, comp = threadIdx.x % 6;
        sh_cs[c][comp] = g_acc[c][comp];
        g_acc[c][comp] = 0.0f;
    }
    __syncthreads();

    // Phase 2: per-cell loss terms.
    if (threadIdx.x < CELLS) {
        int c = threadIdx.x;
        const float inv_hw = 1.0f / (float)HW;
        float sb  = sh_cs[c][0];
        float sf  = sh_cs[c][1];
        float spt = sh_cs[c][2];
        float sp  = sh_cs[c][3];
        float st  = sh_cs[c][4];
        float sa  = sh_cs[c][5];

        float pres = (float)presence_targets[c];
        float pp   = presence_probs[c];

        float bce_mean   = sb * inv_hw;
        float focal_mean = 0.25f * sf * inv_hw;   // FOCAL_ALPHA
        float dice       = 1.f - (2.f * spt + 1e-6f) / (sp + st + 1e-6f);
        float att_mean   = sa * inv_hw;

        // absence BCE (pp in (1e-4, 1-1e-4): reference clamps inert)
        float absence = -(pres * logf(pp) + (1.f - pres) * logf(1.f - pp));

        bool wrong = ((pres == 0.f) && (pp > 0.5f)) || ((pres == 1.f) && (pp < 0.5f));
        float d = pp - 0.5f;
        float conf = wrong ? d * d : 0.f;

        sh_terms[c][0] = pres;
        sh_terms[c][1] = bce_mean   * pres;
        sh_terms[c][2] = dice       * pres;
        sh_terms[c][3] = focal_mean * pres;
        sh_terms[c][4] = absence;
        sh_terms[c][5] = att_mean   * pres;
        sh_terms[c][6] = conf;
    }
    __syncthreads();

    // Phase 3: combine into the scalar.
    if (threadIdx.x == 0) {
        float cnt = 0.f, Sseg = 0.f, Sdice = 0.f, Sfoc = 0.f,
              Sabs = 0.f, Satt = 0.f, Sconf = 0.f;
        for (int i = 0; i < CELLS; i++) {
            cnt   += sh_terms[i][0];
            Sseg  += sh_terms[i][1];
            Sdice += sh_terms[i][2];
            Sfoc  += sh_terms[i][3];
            Sabs  += sh_terms[i][4];
            Satt  += sh_terms[i][5];
            Sconf += sh_terms[i][6];
        }
        float safe = fmaxf(cnt, 1.f);
        float seg_loss   = (cnt > 0.f) ? Sseg  / safe : 0.f;
        float dice_loss  = (cnt > 0.f) ? Sdice / safe : 0.f;
        float focal_loss = (cnt > 0.f) ? Sfoc  / safe : 0.f;
        float n_cells = (float)CELLS;

        out[0] = 1.0f * seg_loss
               + 1.0f * dice_loss
               + 0.5f * focal_loss
               + 1.0f * (Sabs / n_cells)
               + 0.5f * (Satt / n_cells)
               + 0.1f * (Sconf / n_cells);
    }
}

extern "C" void kernel_launch(void* const* d_in, const int* in_sizes, int n_in,
                              void* d_out, int out_size)
{
    // metadata order: seg_logits, seg_probs, seg_targets, presence_probs,
    //                 attention_maps, presence_targets
    // seg_logits (d_in[0]) is redundant: probs = sigmoid(logits) is given and
    // targets are exactly {0,1}, so bce = -log(t ? p : 1-p).
    const float4* probs = (const float4*)d_in[1];
    const float4* targs = (const float4*)d_in[2];
    const float*  pp    = (const float*)d_in[3];
    const float4* attn  = (const float4*)d_in[4];
    const int*    pt    = (const int*)d_in[5];
    float* out = (float*)d_out;

    dim3 grid(CHUNKS, CELLS);
    reduce_kernel<<<grid, THREADS>>>(probs, targs, attn);
    final_kernel<<<1, 384>>>(pp, pt, out);
}